// round 2
// baseline (speedup 1.0000x reference)
#include <cuda_runtime.h>

// OptimizerNetwork: 2-layer LSTM-cell meta-optimizer, N=1e6 rows, H=20.
// R1 showed L1/LDS-bound (78%): every thread re-read all weights from smem.
// R2: process 2 rows/thread so each LDS feeds 2 ffma2 chains (halves LDS/row,
// doubles ILP). fp32 math packed with fma.rn.f32x2 (PTX-only, 2x throughput).

typedef unsigned long long ull;

__device__ __forceinline__ ull pk(float a, float b) {
    ull r; asm("mov.b64 %0, {%1,%2};" : "=l"(r) : "f"(a), "f"(b)); return r;
}
__device__ __forceinline__ void upk(ull p, float& a, float& b) {
    asm("mov.b64 {%0,%1}, %2;" : "=f"(a), "=f"(b) : "l"(p));
}
__device__ __forceinline__ ull ffma2(ull a, ull b, ull c) {
    ull r; asm("fma.rn.f32x2 %0, %1, %2, %3;" : "=l"(r) : "l"(a), "l"(b), "l"(c)); return r;
}
__device__ __forceinline__ float hsum(ull p) { float a, b; upk(p, a, b); return a + b; }

__device__ __forceinline__ float sigm(float x) {
    return __fdividef(1.f, 1.f + __expf(-x));
}
__device__ __forceinline__ float tanhx(float x) {
    return __fdividef(2.f, 1.f + __expf(-2.f * x)) - 1.f;
}

struct __align__(16) SW {
    float Wih1[160];   // [80][2]
    float Whh1[1600];  // [80][20]
    float Wih2[1600];  // [80][20]
    float Whh2[1600];  // [80][20]
    float B1[80];      // bih1+bhh1
    float B2[80];      // bih2+bhh2
    float Wout[20];
    float bout;
};

// One LSTM cell for TWO rows. hc* holds c-in on entry, h-out on exit (alias
// to save registers). Weight pairs loaded once from smem feed both rows.
template <int KPAIR>
__device__ __forceinline__ void cell2(
    const ull* x0, const ull* x1,
    const float* sWih, const float* sWhh, const float* sB,
    const ull* h0_, const ull* h1_,
    ull* hc0, ull* hc1,
    ull* cg0, ull* cg1, bool ok1)
{
#pragma unroll
    for (int jj = 0; jj < 10; ++jj) {
        float gv0[8], gv1[8];
#pragma unroll
        for (int u = 0; u < 2; ++u) {
            const int j = 2 * jj + u;
#pragma unroll
            for (int g = 0; g < 4; ++g) {
                const int r = g * 20 + j;
                ull b = pk(sB[r], 0.f);
                ull a0 = b, a1 = b;
                if (KPAIR == 1) {
                    ull w = *(const ull*)(sWih + r * 2);
                    a0 = ffma2(x0[0], w, a0);
                    a1 = ffma2(x1[0], w, a1);
                } else {
                    const ulonglong2* wi = (const ulonglong2*)(sWih + r * (2 * KPAIR));
#pragma unroll
                    for (int k = 0; k < KPAIR / 2; ++k) {
                        ulonglong2 w = wi[k];
                        a0 = ffma2(x0[2 * k],     w.x, a0);
                        a1 = ffma2(x1[2 * k],     w.x, a1);
                        a0 = ffma2(x0[2 * k + 1], w.y, a0);
                        a1 = ffma2(x1[2 * k + 1], w.y, a1);
                    }
                }
                const ulonglong2* wh = (const ulonglong2*)(sWhh + r * 20);
#pragma unroll
                for (int k = 0; k < 5; ++k) {
                    ulonglong2 w = wh[k];
                    a0 = ffma2(h0_[2 * k],     w.x, a0);
                    a1 = ffma2(h1_[2 * k],     w.x, a1);
                    a0 = ffma2(h0_[2 * k + 1], w.y, a0);
                    a1 = ffma2(h1_[2 * k + 1], w.y, a1);
                }
                gv0[u * 4 + g] = hsum(a0);
                gv1[u * 4 + g] = hsum(a1);
            }
        }
        // row 0 activations + state update
        {
            float i0 = sigm(gv0[0]), f0 = sigm(gv0[1]), g0 = tanhx(gv0[2]), o0 = sigm(gv0[3]);
            float i1 = sigm(gv0[4]), f1 = sigm(gv0[5]), g1 = tanhx(gv0[6]), o1 = sigm(gv0[7]);
            float ca, cb; upk(hc0[jj], ca, cb);
            float cn0 = fmaf(f0, ca, i0 * g0);
            float cn1 = fmaf(f1, cb, i1 * g1);
            cg0[jj] = pk(cn0, cn1);
            hc0[jj] = pk(o0 * tanhx(cn0), o1 * tanhx(cn1));
        }
        // row 1 (store guarded; compute is harmless on zeros)
        {
            float i0 = sigm(gv1[0]), f0 = sigm(gv1[1]), g0 = tanhx(gv1[2]), o0 = sigm(gv1[3]);
            float i1 = sigm(gv1[4]), f1 = sigm(gv1[5]), g1 = tanhx(gv1[6]), o1 = sigm(gv1[7]);
            float ca, cb; upk(hc1[jj], ca, cb);
            float cn0 = fmaf(f0, ca, i0 * g0);
            float cn1 = fmaf(f1, cb, i1 * g1);
            if (ok1) cg1[jj] = pk(cn0, cn1);
            hc1[jj] = pk(o0 * tanhx(cn0), o1 * tanhx(cn1));
        }
    }
}

__device__ __forceinline__ ull preprocess(float x) {
    float ax = fabsf(x);
    float pa, pb;
    if (ax >= 4.5399930e-05f) {            // exp(-10)
        pa = __logf(ax + 1e-8f) * 0.1f;
        pb = (x > 0.f) ? 1.f : -1.f;
    } else {
        pa = -1.f;
        pb = 22026.4658f * x;              // exp(10)
    }
    return pk(pa, pb);
}

__global__ void __launch_bounds__(128)
optnet_kernel(const float* __restrict__ inp,
              const float* __restrict__ h0, const float* __restrict__ h1,
              const float* __restrict__ c0, const float* __restrict__ c1,
              const float* __restrict__ Wih1, const float* __restrict__ Whh1,
              const float* __restrict__ bih1, const float* __restrict__ bhh1,
              const float* __restrict__ Wih2, const float* __restrict__ Whh2,
              const float* __restrict__ bih2, const float* __restrict__ bhh2,
              const float* __restrict__ Wout, const float* __restrict__ bout,
              float* __restrict__ out, int N)
{
    __shared__ SW sw;
    const int tid = threadIdx.x, bd = blockDim.x;
    for (int i = tid; i < 160;  i += bd) sw.Wih1[i] = Wih1[i];
    for (int i = tid; i < 1600; i += bd) sw.Whh1[i] = Whh1[i];
    for (int i = tid; i < 1600; i += bd) sw.Wih2[i] = Wih2[i];
    for (int i = tid; i < 1600; i += bd) sw.Whh2[i] = Whh2[i];
    for (int i = tid; i < 80;   i += bd) { sw.B1[i] = bih1[i] + bhh1[i];
                                           sw.B2[i] = bih2[i] + bhh2[i]; }
    for (int i = tid; i < 20;   i += bd) sw.Wout[i] = Wout[i];
    if (tid == 0) sw.bout = bout[0];
    __syncthreads();

    const size_t base = (size_t)blockIdx.x * (2 * 128);
    const size_t r0 = base + tid;
    const size_t r1 = r0 + 128;
    if (r0 >= (size_t)N) return;
    const bool ok1 = r1 < (size_t)N;

    float* h0n_out = out + (size_t)N;
    float* h1n_out = out + (size_t)N * 21;
    float* c0n_out = out + (size_t)N * 41;
    float* c1n_out = out + (size_t)N * 61;

    // preprocess
    ull xp0[1], xp1[1];
    xp0[0] = preprocess(inp[r0]);
    xp1[0] = preprocess(ok1 ? inp[r1] : 0.f);

    // register state: A = h-in, B = c0->h0n, C = c1->h1n (aliased in-place)
    ull A0[10], A1[10], B0[10], B1[10], C0[10], C1[10];

    const ulonglong2* p;
#pragma unroll
    for (int q = 0; q < 5; ++q) {
        ulonglong2 v;
        v = ((const ulonglong2*)(h0 + r0 * 20))[q]; A0[2*q] = v.x; A0[2*q+1] = v.y;
        v = ((const ulonglong2*)(c0 + r0 * 20))[q]; B0[2*q] = v.x; B0[2*q+1] = v.y;
        if (ok1) {
            v = ((const ulonglong2*)(h0 + r1 * 20))[q]; A1[2*q] = v.x; A1[2*q+1] = v.y;
            v = ((const ulonglong2*)(c0 + r1 * 20))[q]; B1[2*q] = v.x; B1[2*q+1] = v.y;
        } else {
            A1[2*q] = A1[2*q+1] = B1[2*q] = B1[2*q+1] = 0ull;
        }
    }

    // ---- LSTM cell 1 : B becomes h0n ----
    cell2<1>(xp0, xp1, sw.Wih1, sw.Whh1, sw.B1, A0, A1, B0, B1,
             (ull*)(c0n_out + r0 * 20), (ull*)(c0n_out + r1 * 20), ok1);

    // store h0n; load h1 -> A, c1 -> C
#pragma unroll
    for (int q = 0; q < 5; ++q) {
        ulonglong2 v;
        v.x = B0[2*q]; v.y = B0[2*q+1];
        ((ulonglong2*)(h0n_out + r0 * 20))[q] = v;
        if (ok1) { v.x = B1[2*q]; v.y = B1[2*q+1];
                   ((ulonglong2*)(h0n_out + r1 * 20))[q] = v; }
    }
#pragma unroll
    for (int q = 0; q < 5; ++q) {
        ulonglong2 v;
        v = ((const ulonglong2*)(h1 + r0 * 20))[q]; A0[2*q] = v.x; A0[2*q+1] = v.y;
        v = ((const ulonglong2*)(c1 + r0 * 20))[q]; C0[2*q] = v.x; C0[2*q+1] = v.y;
        if (ok1) {
            v = ((const ulonglong2*)(h1 + r1 * 20))[q]; A1[2*q] = v.x; A1[2*q+1] = v.y;
            v = ((const ulonglong2*)(c1 + r1 * 20))[q]; C1[2*q] = v.x; C1[2*q+1] = v.y;
        } else {
            A1[2*q] = A1[2*q+1] = C1[2*q] = C1[2*q+1] = 0ull;
        }
    }

    // ---- LSTM cell 2 : x = h0n (B), h = h1 (A), C becomes h1n ----
    cell2<10>(B0, B1, sw.Wih2, sw.Whh2, sw.B2, A0, A1, C0, C1,
              (ull*)(c1n_out + r0 * 20), (ull*)(c1n_out + r1 * 20), ok1);

    // store h1n
#pragma unroll
    for (int q = 0; q < 5; ++q) {
        ulonglong2 v;
        v.x = C0[2*q]; v.y = C0[2*q+1];
        ((ulonglong2*)(h1n_out + r0 * 20))[q] = v;
        if (ok1) { v.x = C1[2*q]; v.y = C1[2*q+1];
                   ((ulonglong2*)(h1n_out + r1 * 20))[q] = v; }
    }

    // ---- output linear ----
    const ulonglong2* wo = (const ulonglong2*)sw.Wout;
    ull a0 = pk(sw.bout, 0.f), a1 = a0;
#pragma unroll
    for (int k = 0; k < 5; ++k) {
        ulonglong2 w = wo[k];
        a0 = ffma2(C0[2*k],     w.x, a0);
        a1 = ffma2(C1[2*k],     w.x, a1);
        a0 = ffma2(C0[2*k + 1], w.y, a0);
        a1 = ffma2(C1[2*k + 1], w.y, a1);
    }
    out[r0] = hsum(a0);
    if (ok1) out[r1] = hsum(a1);
}

extern "C" void kernel_launch(void* const* d_in, const int* in_sizes, int n_in,
                              void* d_out, int out_size)
{
    const float* inp  = (const float*)d_in[0];
    const float* h0   = (const float*)d_in[1];
    const float* h1   = (const float*)d_in[2];
    const float* c0   = (const float*)d_in[3];
    const float* c1   = (const float*)d_in[4];
    const float* Wih1 = (const float*)d_in[5];
    const float* Whh1 = (const float*)d_in[6];
    const float* bih1 = (const float*)d_in[7];
    const float* bhh1 = (const float*)d_in[8];
    const float* Wih2 = (const float*)d_in[9];
    const float* Whh2 = (const float*)d_in[10];
    const float* bih2 = (const float*)d_in[11];
    const float* bhh2 = (const float*)d_in[12];
    const float* Wout = (const float*)d_in[13];
    const float* bout = (const float*)d_in[14];

    const int N = in_sizes[0];
    const int bd = 128;
    const int rows_per_block = 2 * bd;
    const int blocks = (N + rows_per_block - 1) / rows_per_block;
    optnet_kernel<<<blocks, bd>>>(inp, h0, h1, c0, c1,
                                  Wih1, Whh1, bih1, bhh1,
                                  Wih2, Whh2, bih2, bhh2,
                                  Wout, bout, (float*)d_out, N);
}

// round 3
// speedup vs baseline: 1.6419x; 1.6419x over previous
#include <cuda_runtime.h>

// OptimizerNetwork: 2-layer LSTM-cell meta-optimizer, N=1e6 rows, H=20.
// R1: L1/LDS-bound (78%). R2: 2 rows/thread halved LDS but 184 regs ->
// occ 12.5%, latency-bound (549us). R3: back to 1 row/thread (~110 regs,
// occ 25%) and split weight traffic across TWO ports: Whh1/Whh2 via shared
// (LDS), Wih1/Wih2/biases/Wout via the constant bank (LDC/LDCU, separate
// pipe). fp32 math packed with fma.rn.f32x2 (2 MACs/issue).

typedef unsigned long long ull;

// Weights in constant memory (filled each launch by captured async D2D copies).
__constant__ __align__(16) ull    cWih1v[80];    // [80][2] floats as pairs
__constant__ __align__(16) float4 cWih2v[400];   // [80][20] floats
__constant__ __align__(16) ull    cB1v[80];      // interleaved (bih1[r], bhh1[r])
__constant__ __align__(16) ull    cB2v[80];      // interleaved (bih2[r], bhh2[r])
__constant__ __align__(16) float4 cWoutv[5];     // [20] floats
__constant__ float cBoutv;

__device__ __forceinline__ ull pk(float a, float b) {
    ull r; asm("mov.b64 %0, {%1,%2};" : "=l"(r) : "f"(a), "f"(b)); return r;
}
__device__ __forceinline__ void upk(ull p, float& a, float& b) {
    asm("mov.b64 {%0,%1}, %2;" : "=f"(a), "=f"(b) : "l"(p));
}
__device__ __forceinline__ ull ffma2(ull a, ull b, ull c) {
    ull r; asm("fma.rn.f32x2 %0, %1, %2, %3;" : "=l"(r) : "l"(a), "l"(b), "l"(c)); return r;
}
__device__ __forceinline__ float hsum(ull p) { float a, b; upk(p, a, b); return a + b; }

__device__ __forceinline__ float sigm(float x) {
    return __fdividef(1.f, 1.f + __expf(-x));
}
__device__ __forceinline__ float tanhx(float x) {
    return __fdividef(2.f, 1.f + __expf(-2.f * x)) - 1.f;
}

// One LSTM cell, one row. hc holds c-in on entry and h-out on exit (aliased
// in place to cap register pressure). Whh rows from shared; Wih + combined
// bias from constant bank. hsum(acc) folds both biases (packed in lo/hi).
template <int L>
__device__ __forceinline__ void lstm_cell(
    const ull* __restrict__ xin, const float* __restrict__ sWhh,
    const ull* __restrict__ hin, ull* __restrict__ hc,
    ull* __restrict__ cout_g)
{
#pragma unroll
    for (int jj = 0; jj < 10; ++jj) {
        float gv[8];
#pragma unroll
        for (int u = 0; u < 2; ++u) {
            const int j = 2 * jj + u;
#pragma unroll
            for (int g = 0; g < 4; ++g) {
                const int r = g * 20 + j;
                ull acc = (L == 1) ? cB1v[r] : cB2v[r];   // (bih, bhh) packed
                if (L == 1) {
                    acc = ffma2(xin[0], cWih1v[r], acc);
                } else {
#pragma unroll
                    for (int k = 0; k < 5; ++k) {
                        float4 w = cWih2v[r * 5 + k];
                        acc = ffma2(xin[2 * k],     pk(w.x, w.y), acc);
                        acc = ffma2(xin[2 * k + 1], pk(w.z, w.w), acc);
                    }
                }
                const ulonglong2* wh = (const ulonglong2*)(sWhh + r * 20);
#pragma unroll
                for (int k = 0; k < 5; ++k) {
                    ulonglong2 w = wh[k];
                    acc = ffma2(hin[2 * k],     w.x, acc);
                    acc = ffma2(hin[2 * k + 1], w.y, acc);
                }
                gv[u * 4 + g] = hsum(acc);
            }
        }
        float i0 = sigm(gv[0]), f0 = sigm(gv[1]), g0 = tanhx(gv[2]), o0 = sigm(gv[3]);
        float i1 = sigm(gv[4]), f1 = sigm(gv[5]), g1 = tanhx(gv[6]), o1 = sigm(gv[7]);
        float ca, cb; upk(hc[jj], ca, cb);
        float cn0 = fmaf(f0, ca, i0 * g0);
        float cn1 = fmaf(f1, cb, i1 * g1);
        cout_g[jj] = pk(cn0, cn1);                       // STG.64, frees regs
        hc[jj]     = pk(o0 * tanhx(cn0), o1 * tanhx(cn1));
    }
}

__global__ void __launch_bounds__(128)
optnet_kernel(const float* __restrict__ inp,
              const float* __restrict__ h0, const float* __restrict__ h1,
              const float* __restrict__ c0, const float* __restrict__ c1,
              const float* __restrict__ Whh1g, const float* __restrict__ Whh2g,
              float* __restrict__ out, int N)
{
    __shared__ __align__(16) float sWhh1[1600];
    __shared__ __align__(16) float sWhh2[1600];
    const int tid = threadIdx.x, bd = blockDim.x;
    for (int i = tid; i < 400; i += bd) {
        ((float4*)sWhh1)[i] = ((const float4*)Whh1g)[i];
        ((float4*)sWhh2)[i] = ((const float4*)Whh2g)[i];
    }
    __syncthreads();

    const size_t row = (size_t)blockIdx.x * bd + tid;
    if (row >= (size_t)N) return;

    // ---- preprocess ----
    float x = inp[row];
    float ax = fabsf(x);
    float pa, pb;
    if (ax >= 4.5399930e-05f) {            // exp(-10)
        pa = __logf(ax + 1e-8f) * 0.1f;
        pb = (x > 0.f) ? 1.f : -1.f;
    } else {
        pa = -1.f;
        pb = 22026.4658f * x;              // exp(10)
    }
    ull xp[1]; xp[0] = pk(pa, pb);

    // tuple order: out, h0n, h1n, c0n, c1n
    float* h0n_out = out + (size_t)N;
    float* h1n_out = out + (size_t)N * 21;
    float* c0n_out = out + (size_t)N * 41;
    float* c1n_out = out + (size_t)N * 61;

    ull A[10], B[10], C[10];               // A=h-in, B=c0->h0n, C=c1->h1n

#pragma unroll
    for (int q = 0; q < 5; ++q) {
        ulonglong2 v;
        v = ((const ulonglong2*)(h0 + row * 20))[q]; A[2*q] = v.x; A[2*q+1] = v.y;
        v = ((const ulonglong2*)(c0 + row * 20))[q]; B[2*q] = v.x; B[2*q+1] = v.y;
    }

    // ---- LSTM cell 1: B becomes h0n ----
    lstm_cell<1>(xp, sWhh1, A, B, (ull*)(c0n_out + row * 20));

    // store h0n; load h1 -> A, c1 -> C
#pragma unroll
    for (int q = 0; q < 5; ++q) {
        ulonglong2 v; v.x = B[2*q]; v.y = B[2*q+1];
        ((ulonglong2*)(h0n_out + row * 20))[q] = v;
    }
#pragma unroll
    for (int q = 0; q < 5; ++q) {
        ulonglong2 v;
        v = ((const ulonglong2*)(h1 + row * 20))[q]; A[2*q] = v.x; A[2*q+1] = v.y;
        v = ((const ulonglong2*)(c1 + row * 20))[q]; C[2*q] = v.x; C[2*q+1] = v.y;
    }

    // ---- LSTM cell 2: x = h0n (B), h = h1 (A), C becomes h1n ----
    lstm_cell<2>(B, sWhh2, A, C, (ull*)(c1n_out + row * 20));

    // store h1n
#pragma unroll
    for (int q = 0; q < 5; ++q) {
        ulonglong2 v; v.x = C[2*q]; v.y = C[2*q+1];
        ((ulonglong2*)(h1n_out + row * 20))[q] = v;
    }

    // ---- output linear ----
    ull acc = pk(cBoutv, 0.f);
#pragma unroll
    for (int k = 0; k < 5; ++k) {
        float4 w = cWoutv[k];
        acc = ffma2(C[2*k],     pk(w.x, w.y), acc);
        acc = ffma2(C[2*k + 1], pk(w.z, w.w), acc);
    }
    out[row] = hsum(acc);
}

extern "C" void kernel_launch(void* const* d_in, const int* in_sizes, int n_in,
                              void* d_out, int out_size)
{
    const float* inp  = (const float*)d_in[0];
    const float* h0   = (const float*)d_in[1];
    const float* h1   = (const float*)d_in[2];
    const float* c0   = (const float*)d_in[3];
    const float* c1   = (const float*)d_in[4];
    // d_in[5]=Wih1 [80,2], [6]=Whh1, [7]=bih1, [8]=bhh1,
    // [9]=Wih2, [10]=Whh2, [11]=bih2, [12]=bhh2, [13]=Wout, [14]=bout

    // Stage small weights into the constant bank (async D2D; graph-capturable).
    cudaMemcpyToSymbolAsync(cWih1v, d_in[5], 160 * 4, 0,
                            cudaMemcpyDeviceToDevice, 0);
    cudaMemcpyToSymbolAsync(cWih2v, d_in[9], 1600 * 4, 0,
                            cudaMemcpyDeviceToDevice, 0);
    cudaMemcpyToSymbolAsync(cWoutv, d_in[13], 20 * 4, 0,
                            cudaMemcpyDeviceToDevice, 0);
    cudaMemcpyToSymbolAsync(cBoutv, d_in[14], 4, 0,
                            cudaMemcpyDeviceToDevice, 0);
    // Interleave biases: cB[r] = (bih[r], bhh[r]) via strided 2D copies.
    void* pB1 = nullptr; cudaGetSymbolAddress(&pB1, cB1v);
    void* pB2 = nullptr; cudaGetSymbolAddress(&pB2, cB2v);
    cudaMemcpy2DAsync(pB1, 8, d_in[7], 4, 4, 80, cudaMemcpyDeviceToDevice, 0);
    cudaMemcpy2DAsync((char*)pB1 + 4, 8, d_in[8], 4, 4, 80,
                      cudaMemcpyDeviceToDevice, 0);
    cudaMemcpy2DAsync(pB2, 8, d_in[11], 4, 4, 80, cudaMemcpyDeviceToDevice, 0);
    cudaMemcpy2DAsync((char*)pB2 + 4, 8, d_in[12], 4, 4, 80,
                      cudaMemcpyDeviceToDevice, 0);

    const int N = in_sizes[0];
    const int bd = 128;
    const int blocks = (N + bd - 1) / bd;
    optnet_kernel<<<blocks, bd>>>(inp, h0, h1, c0, c1,
                                  (const float*)d_in[6], (const float*)d_in[10],
                                  (float*)d_out, N);
}

// round 4
// speedup vs baseline: 1.7941x; 1.0927x over previous
#include <cuda_runtime.h>

// OptimizerNetwork: 2-layer LSTM-cell meta-optimizer, N=1e6 rows, H=20.
// R1: LDS-bound 78%. R2: 2 rows/thread -> reg-bound, regressed. R3: const-bank
// weight split, 334us (fma 47%, issue 47%). R4: cut issue count + latency:
//   - tanh.approx.f32 for all activations (1 MUFU each, halves MUFU traffic)
//   - constant weights pre-packed as ulonglong2 (no float4->f32x2 movs)
//   - launch_bounds(128,5) for 5 blocks/SM latency hiding
// fp32 math packed with fma.rn.f32x2 (2 MACs/issue, PTX-only).

typedef unsigned long long ull;

// Weights in constant memory (filled each launch by captured async D2D copies).
__constant__ __align__(16) ull        cWih1v[80];    // [80][2] floats as pairs
__constant__ __align__(16) ulonglong2 cWih2v[400];   // [80][5] f32x2-pair quads
__constant__ __align__(16) ull        cB1v[80];      // interleaved (bih1, bhh1)
__constant__ __align__(16) ull        cB2v[80];      // interleaved (bih2, bhh2)
__constant__ __align__(16) ulonglong2 cWoutv[5];     // [20] floats
__constant__ float cBoutv;

__device__ __forceinline__ ull pk(float a, float b) {
    ull r; asm("mov.b64 %0, {%1,%2};" : "=l"(r) : "f"(a), "f"(b)); return r;
}
__device__ __forceinline__ void upk(ull p, float& a, float& b) {
    asm("mov.b64 {%0,%1}, %2;" : "=f"(a), "=f"(b) : "l"(p));
}
__device__ __forceinline__ ull ffma2(ull a, ull b, ull c) {
    ull r; asm("fma.rn.f32x2 %0, %1, %2, %3;" : "=l"(r) : "l"(a), "l"(b), "l"(c)); return r;
}
__device__ __forceinline__ float hsum(ull p) { float a, b; upk(p, a, b); return a + b; }

__device__ __forceinline__ float tanha(float x) {
    float r; asm("tanh.approx.f32 %0, %1;" : "=f"(r) : "f"(x)); return r;
}
__device__ __forceinline__ float sigm(float x) {
    return fmaf(0.5f, tanha(0.5f * x), 0.5f);
}

// One LSTM cell, one row. hc holds c-in on entry and h-out on exit (aliased
// in place to cap register pressure). Whh rows from shared; Wih + combined
// bias from constant bank. hsum(acc) folds both biases (packed lo/hi).
template <int L>
__device__ __forceinline__ void lstm_cell(
    const ull* __restrict__ xin, const float* __restrict__ sWhh,
    const ull* __restrict__ hin, ull* __restrict__ hc,
    ull* __restrict__ cout_g)
{
#pragma unroll
    for (int jj = 0; jj < 10; ++jj) {
        float gv[8];
#pragma unroll
        for (int u = 0; u < 2; ++u) {
            const int j = 2 * jj + u;
#pragma unroll
            for (int g = 0; g < 4; ++g) {
                const int r = g * 20 + j;
                ull acc = (L == 1) ? cB1v[r] : cB2v[r];   // (bih, bhh) packed
                if (L == 1) {
                    acc = ffma2(xin[0], cWih1v[r], acc);
                } else {
#pragma unroll
                    for (int k = 0; k < 5; ++k) {
                        ulonglong2 w = cWih2v[r * 5 + k];
                        acc = ffma2(xin[2 * k],     w.x, acc);
                        acc = ffma2(xin[2 * k + 1], w.y, acc);
                    }
                }
                const ulonglong2* wh = (const ulonglong2*)(sWhh + r * 20);
#pragma unroll
                for (int k = 0; k < 5; ++k) {
                    ulonglong2 w = wh[k];
                    acc = ffma2(hin[2 * k],     w.x, acc);
                    acc = ffma2(hin[2 * k + 1], w.y, acc);
                }
                gv[u * 4 + g] = hsum(acc);
            }
        }
        float i0 = sigm(gv[0]), f0 = sigm(gv[1]), g0 = tanha(gv[2]), o0 = sigm(gv[3]);
        float i1 = sigm(gv[4]), f1 = sigm(gv[5]), g1 = tanha(gv[6]), o1 = sigm(gv[7]);
        float ca, cb; upk(hc[jj], ca, cb);
        float cn0 = fmaf(f0, ca, i0 * g0);
        float cn1 = fmaf(f1, cb, i1 * g1);
        cout_g[jj] = pk(cn0, cn1);                       // STG.64, frees regs
        hc[jj]     = pk(o0 * tanha(cn0), o1 * tanha(cn1));
    }
}

__global__ void __launch_bounds__(128, 5)
optnet_kernel(const float* __restrict__ inp,
              const float* __restrict__ h0, const float* __restrict__ h1,
              const float* __restrict__ c0, const float* __restrict__ c1,
              const float* __restrict__ Whh1g, const float* __restrict__ Whh2g,
              float* __restrict__ out, int N)
{
    __shared__ __align__(16) float sWhh1[1600];
    __shared__ __align__(16) float sWhh2[1600];
    const int tid = threadIdx.x, bd = blockDim.x;
    for (int i = tid; i < 400; i += bd) {
        ((float4*)sWhh1)[i] = ((const float4*)Whh1g)[i];
        ((float4*)sWhh2)[i] = ((const float4*)Whh2g)[i];
    }
    __syncthreads();

    const size_t row = (size_t)blockIdx.x * bd + tid;
    if (row >= (size_t)N) return;

    // ---- preprocess ----
    float x = inp[row];
    float ax = fabsf(x);
    float pa, pb;
    if (ax >= 4.5399930e-05f) {            // exp(-10)
        pa = __logf(ax + 1e-8f) * 0.1f;
        pb = (x > 0.f) ? 1.f : -1.f;
    } else {
        pa = -1.f;
        pb = 22026.4658f * x;              // exp(10)
    }
    ull xp[1]; xp[0] = pk(pa, pb);

    // tuple order: out, h0n, h1n, c0n, c1n
    float* h0n_out = out + (size_t)N;
    float* h1n_out = out + (size_t)N * 21;
    float* c0n_out = out + (size_t)N * 41;
    float* c1n_out = out + (size_t)N * 61;

    ull A[10], B[10], C[10];               // A=h-in, B=c0->h0n, C=c1->h1n

#pragma unroll
    for (int q = 0; q < 5; ++q) {
        ulonglong2 v;
        v = ((const ulonglong2*)(h0 + row * 20))[q]; A[2*q] = v.x; A[2*q+1] = v.y;
        v = ((const ulonglong2*)(c0 + row * 20))[q]; B[2*q] = v.x; B[2*q+1] = v.y;
    }

    // ---- LSTM cell 1: B becomes h0n ----
    lstm_cell<1>(xp, sWhh1, A, B, (ull*)(c0n_out + row * 20));

    // store h0n; load h1 -> A, c1 -> C
#pragma unroll
    for (int q = 0; q < 5; ++q) {
        ulonglong2 v; v.x = B[2*q]; v.y = B[2*q+1];
        ((ulonglong2*)(h0n_out + row * 20))[q] = v;
    }
#pragma unroll
    for (int q = 0; q < 5; ++q) {
        ulonglong2 v;
        v = ((const ulonglong2*)(h1 + row * 20))[q]; A[2*q] = v.x; A[2*q+1] = v.y;
        v = ((const ulonglong2*)(c1 + row * 20))[q]; C[2*q] = v.x; C[2*q+1] = v.y;
    }

    // ---- LSTM cell 2: x = h0n (B), h = h1 (A), C becomes h1n ----
    lstm_cell<2>(B, sWhh2, A, C, (ull*)(c1n_out + row * 20));

    // store h1n
#pragma unroll
    for (int q = 0; q < 5; ++q) {
        ulonglong2 v; v.x = C[2*q]; v.y = C[2*q+1];
        ((ulonglong2*)(h1n_out + row * 20))[q] = v;
    }

    // ---- output linear ----
    ull acc = pk(cBoutv, 0.f);
#pragma unroll
    for (int k = 0; k < 5; ++k) {
        ulonglong2 w = cWoutv[k];
        acc = ffma2(C[2*k],     w.x, acc);
        acc = ffma2(C[2*k + 1], w.y, acc);
    }
    out[row] = hsum(acc);
}

extern "C" void kernel_launch(void* const* d_in, const int* in_sizes, int n_in,
                              void* d_out, int out_size)
{
    const float* inp  = (const float*)d_in[0];
    const float* h0   = (const float*)d_in[1];
    const float* h1   = (const float*)d_in[2];
    const float* c0   = (const float*)d_in[3];
    const float* c1   = (const float*)d_in[4];
    // d_in[5]=Wih1 [80,2], [6]=Whh1, [7]=bih1, [8]=bhh1,
    // [9]=Wih2, [10]=Whh2, [11]=bih2, [12]=bhh2, [13]=Wout, [14]=bout

    // Stage small weights into the constant bank (async D2D; graph-capturable).
    cudaMemcpyToSymbolAsync(cWih1v, d_in[5], 160 * 4, 0,
                            cudaMemcpyDeviceToDevice, 0);
    cudaMemcpyToSymbolAsync(cWih2v, d_in[9], 1600 * 4, 0,
                            cudaMemcpyDeviceToDevice, 0);
    cudaMemcpyToSymbolAsync(cWoutv, d_in[13], 20 * 4, 0,
                            cudaMemcpyDeviceToDevice, 0);
    cudaMemcpyToSymbolAsync(cBoutv, d_in[14], 4, 0,
                            cudaMemcpyDeviceToDevice, 0);
    // Interleave biases: cB[r] = (bih[r], bhh[r]) via strided 2D copies.
    void* pB1 = nullptr; cudaGetSymbolAddress(&pB1, cB1v);
    void* pB2 = nullptr; cudaGetSymbolAddress(&pB2, cB2v);
    cudaMemcpy2DAsync(pB1, 8, d_in[7], 4, 4, 80, cudaMemcpyDeviceToDevice, 0);
    cudaMemcpy2DAsync((char*)pB1 + 4, 8, d_in[8], 4, 4, 80,
                      cudaMemcpyDeviceToDevice, 0);
    cudaMemcpy2DAsync(pB2, 8, d_in[11], 4, 4, 80, cudaMemcpyDeviceToDevice, 0);
    cudaMemcpy2DAsync((char*)pB2 + 4, 8, d_in[12], 4, 4, 80,
                      cudaMemcpyDeviceToDevice, 0);

    const int N = in_sizes[0];
    const int bd = 128;
    const int blocks = (N + bd - 1) / bd;
    optnet_kernel<<<blocks, bd>>>(inp, h0, h1, c0, c1,
                                  (const float*)d_in[6], (const float*)d_in[10],
                                  (float*)d_out, N);
}